// round 4
// baseline (speedup 1.0000x reference)
#include <cuda_runtime.h>
#include <cuda_bf16.h>
#include <math.h>
#include <stdint.h>

// Problem constants: B=8, Sq=Skv=2048, DIM=1024, CTX=768
#define BATCH 8
#define SEQ   2048
#define DIM   1024
#define CTX   768
#define MROWS (BATCH * SEQ)   // 16384

// ---------------------------------------------------------------------------
// Device scratch (allocation-free: __device__ globals)
// ---------------------------------------------------------------------------
__device__ __nv_bfloat16 g_xh[(long long)MROWS * DIM];
__device__ __nv_bfloat16 g_xl[(long long)MROWS * DIM];
__device__ __nv_bfloat16 g_ch[(long long)MROWS * CTX];
__device__ __nv_bfloat16 g_cl[(long long)MROWS * CTX];
__device__ __nv_bfloat16 g_wqh[(long long)DIM * DIM];
__device__ __nv_bfloat16 g_wql[(long long)DIM * DIM];
__device__ __nv_bfloat16 g_wkh[(long long)DIM * CTX];
__device__ __nv_bfloat16 g_wkl[(long long)DIM * CTX];
__device__ __nv_bfloat16 g_wvh[(long long)DIM * CTX];
__device__ __nv_bfloat16 g_wvl[(long long)DIM * CTX];
__device__ __nv_bfloat16 g_woh[(long long)DIM * DIM];
__device__ __nv_bfloat16 g_wol[(long long)DIM * DIM];
__device__ __nv_bfloat16 g_qh[(long long)MROWS * DIM];
__device__ __nv_bfloat16 g_ql[(long long)MROWS * DIM];
__device__ __nv_bfloat16 g_kh[(long long)MROWS * DIM];
__device__ __nv_bfloat16 g_kl[(long long)MROWS * DIM];
__device__ __nv_bfloat16 g_vh[(long long)MROWS * DIM];
__device__ __nv_bfloat16 g_vl[(long long)MROWS * DIM];
__device__ __nv_bfloat16 g_vth[(long long)MROWS * DIM];  // per-batch [DIM, SEQ]
__device__ __nv_bfloat16 g_vtl[(long long)MROWS * DIM];
__device__ __nv_bfloat16 g_oh[(long long)MROWS * DIM];
__device__ __nv_bfloat16 g_ol[(long long)MROWS * DIM];
__device__ __nv_bfloat16 g_ph[(long long)BATCH * SEQ * SEQ];
__device__ __nv_bfloat16 g_pl[(long long)BATCH * SEQ * SEQ];
__device__ float         g_s [(long long)BATCH * SEQ * SEQ];

// ---------------------------------------------------------------------------
// PTX helpers (sm_80-era: compile clean at compute_103)
// ---------------------------------------------------------------------------
__device__ __forceinline__ uint32_t smem_u32(const void* p) {
    uint32_t a;
    asm("{ .reg .u64 t; cvta.to.shared.u64 t, %1; cvt.u32.u64 %0, t; }" : "=r"(a) : "l"(p));
    return a;
}
__device__ __forceinline__ void cpasync16(uint32_t saddr, const void* g) {
    asm volatile("cp.async.cg.shared.global [%0], [%1], 16;" :: "r"(saddr), "l"(g));
}
#define CP_COMMIT() asm volatile("cp.async.commit_group;" ::: "memory")
#define CP_WAIT(n)  asm volatile("cp.async.wait_group %0;" :: "n"(n) : "memory")

__device__ __forceinline__ void ldsm_x4(uint32_t* r, uint32_t addr) {
    asm volatile("ldmatrix.sync.aligned.m8n8.x4.shared.b16 {%0,%1,%2,%3}, [%4];"
        : "=r"(r[0]), "=r"(r[1]), "=r"(r[2]), "=r"(r[3]) : "r"(addr));
}
__device__ __forceinline__ void ldsm_x2(uint32_t* r, uint32_t addr) {
    asm volatile("ldmatrix.sync.aligned.m8n8.x2.shared.b16 {%0,%1}, [%2];"
        : "=r"(r[0]), "=r"(r[1]) : "r"(addr));
}
__device__ __forceinline__ void mma16816(float* d, const uint32_t* a, const uint32_t* b) {
    asm volatile("mma.sync.aligned.m16n8k16.row.col.f32.bf16.bf16.f32 "
        "{%0,%1,%2,%3}, {%4,%5,%6,%7}, {%8,%9}, {%0,%1,%2,%3};"
        : "+f"(d[0]), "+f"(d[1]), "+f"(d[2]), "+f"(d[3])
        : "r"(a[0]), "r"(a[1]), "r"(a[2]), "r"(a[3]), "r"(b[0]), "r"(b[1]));
}

union U8 { uint4 v; __nv_bfloat16 h[8]; };

__device__ __forceinline__ void split1(float v, __nv_bfloat16& h, __nv_bfloat16& l) {
    h = __float2bfloat16(v);
    l = __float2bfloat16(v - __bfloat162float(h));
}

// ---------------------------------------------------------------------------
// Split fp32 -> bf16 hi/lo  (n divisible by 2048)
// ---------------------------------------------------------------------------
__global__ void __launch_bounds__(256)
split_f32(const float* __restrict__ in, __nv_bfloat16* __restrict__ hi,
          __nv_bfloat16* __restrict__ lo)
{
    long long i = ((long long)blockIdx.x * 256 + threadIdx.x) * 8;
    float4 a = *(const float4*)(in + i);
    float4 b = *(const float4*)(in + i + 4);
    float v[8] = {a.x, a.y, a.z, a.w, b.x, b.y, b.z, b.w};
    U8 uh, ul;
#pragma unroll
    for (int e = 0; e < 8; ++e) split1(v[e], uh.h[e], ul.h[e]);
    *(uint4*)(hi + i) = uh.v;
    *(uint4*)(lo + i) = ul.v;
}

// ---------------------------------------------------------------------------
// Transpose V (hi/lo selected by blockIdx.z): [16384,1024] -> per-batch [1024,2048]
// ---------------------------------------------------------------------------
__global__ void __launch_bounds__(256)
transpose_v(const __nv_bfloat16* __restrict__ inH, const __nv_bfloat16* __restrict__ inL,
            __nv_bfloat16* __restrict__ outH, __nv_bfloat16* __restrict__ outL)
{
    __shared__ __nv_bfloat16 s[64][80];
    const __nv_bfloat16* in  = blockIdx.z ? inL : inH;
    __nv_bfloat16*       out = blockIdx.z ? outL : outH;
    const int tBase = blockIdx.y * 64;          // global token row
    const int dBase = blockIdx.x * 64;          // dim
    const int b  = tBase >> 11;
    const int t0 = tBase & 2047;
    const int tid = threadIdx.x;
#pragma unroll
    for (int p = 0; p < 2; ++p) {
        int task = tid + p * 256;
        int r = task >> 3, cg = task & 7;
        uint4 v = *(const uint4*)(in + (long long)(tBase + r) * DIM + dBase + cg * 8);
        *(uint4*)&s[r][cg * 8] = v;
    }
    __syncthreads();
#pragma unroll
    for (int p = 0; p < 2; ++p) {
        int task = tid + p * 256;
        int d = task >> 3, tg = task & 7;
        U8 u;
#pragma unroll
        for (int e = 0; e < 8; ++e) u.h[e] = s[tg * 8 + e][d];
        *(uint4*)(out + (long long)b * (DIM * SEQ) + (long long)(dBase + d) * SEQ + t0 + tg * 8) = u.v;
    }
}

// ---------------------------------------------------------------------------
// Row softmax over 2048 cols -> bf16 hi/lo output
// ---------------------------------------------------------------------------
__global__ void __launch_bounds__(256)
softmax_split(const float* __restrict__ S, __nv_bfloat16* __restrict__ Ph,
              __nv_bfloat16* __restrict__ Pl, float scale)
{
    const long long row = blockIdx.x;
    const float* p = S + row * (long long)SEQ;
    const int tid = threadIdx.x, lane = tid & 31, wid = tid >> 5;
    __shared__ float buf[8];

    float x[8];
#pragma unroll
    for (int i = 0; i < 8; ++i) x[i] = p[tid + i * 256] * scale;

    float m = x[0];
#pragma unroll
    for (int i = 1; i < 8; ++i) m = fmaxf(m, x[i]);
#pragma unroll
    for (int off = 16; off > 0; off >>= 1)
        m = fmaxf(m, __shfl_xor_sync(0xFFFFFFFFu, m, off));
    if (lane == 0) buf[wid] = m;
    __syncthreads();
    float mfull = buf[0];
#pragma unroll
    for (int w = 1; w < 8; ++w) mfull = fmaxf(mfull, buf[w]);
    __syncthreads();

    float e[8], sum = 0.0f;
#pragma unroll
    for (int i = 0; i < 8; ++i) { e[i] = __expf(x[i] - mfull); sum += e[i]; }
#pragma unroll
    for (int off = 16; off > 0; off >>= 1)
        sum += __shfl_xor_sync(0xFFFFFFFFu, sum, off);
    if (lane == 0) buf[wid] = sum;
    __syncthreads();
    float sfull = 0.0f;
#pragma unroll
    for (int w = 0; w < 8; ++w) sfull += buf[w];
    const float inv = 1.0f / sfull;

    __nv_bfloat16* ph = Ph + row * (long long)SEQ;
    __nv_bfloat16* pl = Pl + row * (long long)SEQ;
#pragma unroll
    for (int i = 0; i < 8; ++i) {
        __nv_bfloat16 h, l;
        split1(e[i] * inv, h, l);
        ph[tid + i * 256] = h;
        pl[tid + i * 256] = l;
    }
}

// ---------------------------------------------------------------------------
// Split-bf16 TN GEMM on mma.sync tensor cores:
//   D[M,N] = (Ah+Al)[M,K] * (Bh+Bl)[N,K]^T  (3-term: AhBh + AhBl + AlBh)
// Tile 128x128, BK=32, 8 warps (2x4 -> warp tile 64x32).
// 3-stage cp.async pipeline, ONE __syncthreads per stage.
// SMEM row layout: 128B per matrix row = 32 hi bf16 | 32 lo bf16, XOR-swizzled
//   phys(r, chunk16B c in 0..7) = r*128 + ((c ^ (r&7)) * 16);  lo = hi ^ 64.
// Fully conflict-free for cp.async stores and ldmatrix.
// EPI=0: fp32 C (+bias).  EPI=1: bf16 hi/lo C (+bias).
// ---------------------------------------------------------------------------
#define MAT_BYTES   16384          // 128 rows * 128 B (hi|lo interleaved)
#define STAGE_BYTES (2 * MAT_BYTES)
#define NSTAGE 3
#define SMEM_TOTAL  (NSTAGE * STAGE_BYTES)
#define A_OFF 0
#define B_OFF MAT_BYTES

template<int EPI>
__global__ void __launch_bounds__(256, 2)
gemm_mma(const __nv_bfloat16* __restrict__ Ah, const __nv_bfloat16* __restrict__ Al,
         const __nv_bfloat16* __restrict__ Bh, const __nv_bfloat16* __restrict__ Bl,
         float* __restrict__ Cf, __nv_bfloat16* __restrict__ Ch,
         __nv_bfloat16* __restrict__ Cl, const float* __restrict__ bias,
         int K, int N, long long sA, long long sB, long long sC)
{
    extern __shared__ __align__(128) char smem[];
    const uint32_t sbase = smem_u32(smem);

    const int tid  = threadIdx.x;
    const int wid  = tid >> 5;
    const int lane = tid & 31;
    const int wm   = wid >> 2;      // 0..1
    const int wn   = wid & 3;       // 0..3

    const int bm0 = blockIdx.y * 128;
    const int bn0 = blockIdx.x * 128;
    const long long zA = blockIdx.z * sA, zB = blockIdx.z * sB, zC = blockIdx.z * sC;

    // ---- loader mapping: thread -> (row, half) ; 4 x 16B chunks each matrix ----
    const int ldr  = tid >> 1;           // 0..127 row within tile
    const int half = tid & 1;            // 0 = hi, 1 = lo
    const __nv_bfloat16* srcA = (half ? Al : Ah) + zA + (long long)(bm0 + ldr) * K;
    const __nv_bfloat16* srcB = (half ? Bl : Bh) + zB + (long long)(bn0 + ldr) * K;
    const uint32_t ldSwz  = (uint32_t)(ldr & 7) << 4;    // swizzle sel * 16
    const uint32_t ldHalf = (uint32_t)half << 6;         // hi/lo 64B select
    const uint32_t ldRowB = (uint32_t)ldr * 128;

    // ---- ldmatrix address bases ----
    const int aRow = wm * 64 + (lane & 15);
    const uint32_t aSwz = (uint32_t)(aRow & 7) << 4;
    const uint32_t aSel = (uint32_t)(lane >> 4);          // extra k-chunk
    const int bRow = wn * 32 + (lane & 7);
    const uint32_t bSwz = (uint32_t)(lane & 7) << 4;
    const uint32_t bSel = (uint32_t)((lane >> 3) & 1);

    float acc[4][4][4];
#pragma unroll
    for (int i = 0; i < 4; ++i)
#pragma unroll
        for (int j = 0; j < 4; ++j)
#pragma unroll
            for (int r = 0; r < 4; ++r) acc[i][j][r] = 0.0f;

    const int nStages = K >> 5;

    auto load_stage = [&](int s) {
        const uint32_t sb = sbase + (uint32_t)(s % NSTAGE) * STAGE_BYTES;
        const int k0 = s << 5;
#pragma unroll
        for (int j = 0; j < 4; ++j) {
            const uint32_t off = ldRowB + ((((uint32_t)j << 4) ^ ldSwz) ^ ldHalf);
            cpasync16(sb + A_OFF + off, srcA + k0 + j * 8);
            cpasync16(sb + B_OFF + off, srcB + k0 + j * 8);
        }
        CP_COMMIT();
    };

    load_stage(0);
    if (nStages > 1) load_stage(1);

    for (int s = 0; s < nStages; ++s) {
        if (s + 1 < nStages) { CP_WAIT(1); } else { CP_WAIT(0); }
        __syncthreads();
        if (s + 2 < nStages) load_stage(s + 2);

        const uint32_t sb = sbase + (uint32_t)(s % NSTAGE) * STAGE_BYTES;
#pragma unroll
        for (int kb = 0; kb < 2; ++kb) {
            // B fragments: hi & lo for 4 j-tiles
            uint32_t bh[4][2], bl[4][2];
#pragma unroll
            for (int j = 0; j < 4; ++j) {
                const uint32_t chunk = ((uint32_t)(kb * 2) + bSel) << 4;
                const uint32_t ba = sb + B_OFF + (uint32_t)(bRow + j * 8) * 128
                                  + (chunk ^ bSwz);
                ldsm_x2(bh[j], ba);
                ldsm_x2(bl[j], ba ^ 64);
            }
#pragma unroll
            for (int i = 0; i < 4; ++i) {
                const uint32_t chunk = ((uint32_t)(kb * 2) + aSel) << 4;
                const uint32_t aa = sb + A_OFF + (uint32_t)(aRow + i * 16) * 128
                                  + (chunk ^ aSwz);
                uint32_t ah[4], al[4];
                ldsm_x4(ah, aa);
                ldsm_x4(al, aa ^ 64);
#pragma unroll
                for (int j = 0; j < 4; ++j) {
                    mma16816(acc[i][j], ah, bh[j]);
                    mma16816(acc[i][j], ah, bl[j]);
                    mma16816(acc[i][j], al, bh[j]);
                }
            }
        }
    }

    // ---- epilogue ----
    const int r0base = bm0 + wm * 64 + (lane >> 2);
    const int c0base = bn0 + wn * 32 + (lane & 3) * 2;

    float bz[4][2];
#pragma unroll
    for (int j = 0; j < 4; ++j) {
        const int c = c0base + j * 8;
        bz[j][0] = bias ? __ldg(bias + c)     : 0.0f;
        bz[j][1] = bias ? __ldg(bias + c + 1) : 0.0f;
    }

#pragma unroll
    for (int i = 0; i < 4; ++i) {
        const long long r0 = r0base + i * 16;
        const long long r1 = r0 + 8;
#pragma unroll
        for (int j = 0; j < 4; ++j) {
            const int c = c0base + j * 8;
            float v00 = acc[i][j][0] + bz[j][0];
            float v01 = acc[i][j][1] + bz[j][1];
            float v10 = acc[i][j][2] + bz[j][0];
            float v11 = acc[i][j][3] + bz[j][1];
            if (EPI == 0) {
                *(float2*)(Cf + zC + r0 * N + c) = make_float2(v00, v01);
                *(float2*)(Cf + zC + r1 * N + c) = make_float2(v10, v11);
            } else {
                __nv_bfloat16 h0, l0, h1, l1;
                split1(v00, h0, l0); split1(v01, h1, l1);
                *(__nv_bfloat162*)(Ch + zC + r0 * N + c) = __nv_bfloat162(h0, h1);
                *(__nv_bfloat162*)(Cl + zC + r0 * N + c) = __nv_bfloat162(l0, l1);
                split1(v10, h0, l0); split1(v11, h1, l1);
                *(__nv_bfloat162*)(Ch + zC + r1 * N + c) = __nv_bfloat162(h0, h1);
                *(__nv_bfloat162*)(Cl + zC + r1 * N + c) = __nv_bfloat162(l0, l1);
            }
        }
    }
}

// ---------------------------------------------------------------------------
// kernel_launch
// ---------------------------------------------------------------------------
extern "C" void kernel_launch(void* const* d_in, const int* in_sizes, int n_in,
                              void* d_out, int out_size)
{
    const float* x   = (const float*)d_in[0];
    const float* ctx = (const float*)d_in[1];
    const float* Wq  = (const float*)d_in[2];
    const float* bq  = (const float*)d_in[3];
    const float* Wk  = (const float*)d_in[4];
    const float* bk  = (const float*)d_in[5];
    const float* Wv  = (const float*)d_in[6];
    const float* bv  = (const float*)d_in[7];
    const float* Wo  = (const float*)d_in[8];
    const float* bo  = (const float*)d_in[9];
    float* out = (float*)d_out;

    __nv_bfloat16 *xh, *xl, *ch, *cl, *wqh, *wql, *wkh, *wkl, *wvh, *wvl, *woh, *wol;
    __nv_bfloat16 *qh, *ql, *kh, *kl, *vh, *vl, *vth, *vtl, *oh, *ol, *ph, *pl;
    float* S;
    cudaGetSymbolAddress((void**)&xh, g_xh);   cudaGetSymbolAddress((void**)&xl, g_xl);
    cudaGetSymbolAddress((void**)&ch, g_ch);   cudaGetSymbolAddress((void**)&cl, g_cl);
    cudaGetSymbolAddress((void**)&wqh, g_wqh); cudaGetSymbolAddress((void**)&wql, g_wql);
    cudaGetSymbolAddress((void**)&wkh, g_wkh); cudaGetSymbolAddress((void**)&wkl, g_wkl);
    cudaGetSymbolAddress((void**)&wvh, g_wvh); cudaGetSymbolAddress((void**)&wvl, g_wvl);
    cudaGetSymbolAddress((void**)&woh, g_woh); cudaGetSymbolAddress((void**)&wol, g_wol);
    cudaGetSymbolAddress((void**)&qh, g_qh);   cudaGetSymbolAddress((void**)&ql, g_ql);
    cudaGetSymbolAddress((void**)&kh, g_kh);   cudaGetSymbolAddress((void**)&kl, g_kl);
    cudaGetSymbolAddress((void**)&vh, g_vh);   cudaGetSymbolAddress((void**)&vl, g_vl);
    cudaGetSymbolAddress((void**)&vth, g_vth); cudaGetSymbolAddress((void**)&vtl, g_vtl);
    cudaGetSymbolAddress((void**)&oh, g_oh);   cudaGetSymbolAddress((void**)&ol, g_ol);
    cudaGetSymbolAddress((void**)&ph, g_ph);   cudaGetSymbolAddress((void**)&pl, g_pl);
    cudaGetSymbolAddress((void**)&S, g_s);

    cudaFuncSetAttribute(gemm_mma<0>, cudaFuncAttributeMaxDynamicSharedMemorySize, SMEM_TOTAL);
    cudaFuncSetAttribute(gemm_mma<1>, cudaFuncAttributeMaxDynamicSharedMemorySize, SMEM_TOTAL);

    // 1) split inputs & weights to bf16 hi/lo
    split_f32<<<(MROWS * (long long)DIM) / 2048, 256>>>(x, xh, xl);
    split_f32<<<(MROWS * (long long)CTX) / 2048, 256>>>(ctx, ch, cl);
    split_f32<<<(DIM * (long long)DIM) / 2048, 256>>>(Wq, wqh, wql);
    split_f32<<<(DIM * (long long)CTX) / 2048, 256>>>(Wk, wkh, wkl);
    split_f32<<<(DIM * (long long)CTX) / 2048, 256>>>(Wv, wvh, wvl);
    split_f32<<<(DIM * (long long)DIM) / 2048, 256>>>(Wo, woh, wol);

    // 2) projections -> bf16 hi/lo (Q, K, V)
    {
        dim3 grd(DIM / 128, MROWS / 128, 1);
        gemm_mma<1><<<grd, 256, SMEM_TOTAL>>>(xh, xl, wqh, wql, nullptr, qh, ql, bq,
                                              DIM, DIM, 0, 0, 0);
        gemm_mma<1><<<grd, 256, SMEM_TOTAL>>>(ch, cl, wkh, wkl, nullptr, kh, kl, bk,
                                              CTX, DIM, 0, 0, 0);
        gemm_mma<1><<<grd, 256, SMEM_TOTAL>>>(ch, cl, wvh, wvl, nullptr, vh, vl, bv,
                                              CTX, DIM, 0, 0, 0);
    }

    // 3) transpose V per batch -> [DIM, SEQ]
    transpose_v<<<dim3(DIM / 64, MROWS / 64, 2), 256>>>(vh, vl, vth, vtl);

    // 4) scores S = Q K^T (fp32)
    {
        dim3 grd(SEQ / 128, SEQ / 128, BATCH);
        gemm_mma<0><<<grd, 256, SMEM_TOTAL>>>(qh, ql, kh, kl, S, nullptr, nullptr, nullptr,
                                              DIM, SEQ,
                                              (long long)SEQ * DIM, (long long)SEQ * DIM,
                                              (long long)SEQ * SEQ);
    }

    // 5) softmax -> P hi/lo
    softmax_split<<<BATCH * SEQ, 256>>>(S, ph, pl, 1.0f / sqrtf((float)DIM));

    // 6) O = P V  -> bf16 hi/lo
    {
        dim3 grd(DIM / 128, SEQ / 128, BATCH);
        gemm_mma<1><<<grd, 256, SMEM_TOTAL>>>(ph, pl, vth, vtl, nullptr, oh, ol, nullptr,
                                              SEQ, DIM,
                                              (long long)SEQ * SEQ, (long long)DIM * SEQ,
                                              (long long)SEQ * DIM);
    }

    // 7) out = O Wo^T + bo (fp32 -> d_out)
    {
        dim3 grd(DIM / 128, MROWS / 128, 1);
        gemm_mma<0><<<grd, 256, SMEM_TOTAL>>>(oh, ol, woh, wol, out, nullptr, nullptr, bo,
                                              DIM, DIM, 0, 0, 0);
    }
}

// round 5
// speedup vs baseline: 1.2882x; 1.2882x over previous
#include <cuda_runtime.h>
#include <cuda_bf16.h>
#include <math.h>
#include <stdint.h>

// Problem constants: B=8, Sq=Skv=2048, DIM=1024, CTX=768
#define BATCH 8
#define SEQ   2048
#define DIM   1024
#define CTX   768
#define MROWS (BATCH * SEQ)   // 16384

// ---------------------------------------------------------------------------
// Device scratch (allocation-free: __device__ globals)
// ---------------------------------------------------------------------------
__device__ __nv_bfloat16 g_xh[(long long)MROWS * DIM];
__device__ __nv_bfloat16 g_xl[(long long)MROWS * DIM];
__device__ __nv_bfloat16 g_ch[(long long)MROWS * CTX];
__device__ __nv_bfloat16 g_cl[(long long)MROWS * CTX];
__device__ __nv_bfloat16 g_wqh[(long long)DIM * DIM];
__device__ __nv_bfloat16 g_wql[(long long)DIM * DIM];
__device__ __nv_bfloat16 g_wkh[(long long)DIM * CTX];
__device__ __nv_bfloat16 g_wkl[(long long)DIM * CTX];
__device__ __nv_bfloat16 g_wvh[(long long)DIM * CTX];
__device__ __nv_bfloat16 g_wvl[(long long)DIM * CTX];
__device__ __nv_bfloat16 g_woh[(long long)DIM * DIM];
__device__ __nv_bfloat16 g_wol[(long long)DIM * DIM];
__device__ __nv_bfloat16 g_qh[(long long)MROWS * DIM];
__device__ __nv_bfloat16 g_ql[(long long)MROWS * DIM];
__device__ __nv_bfloat16 g_kh[(long long)MROWS * DIM];
__device__ __nv_bfloat16 g_kl[(long long)MROWS * DIM];
__device__ __nv_bfloat16 g_vh[(long long)MROWS * DIM];
__device__ __nv_bfloat16 g_vl[(long long)MROWS * DIM];
__device__ __nv_bfloat16 g_vth[(long long)MROWS * DIM];  // per-batch [DIM, SEQ]
__device__ __nv_bfloat16 g_vtl[(long long)MROWS * DIM];
__device__ __nv_bfloat16 g_oh[(long long)MROWS * DIM];
__device__ __nv_bfloat16 g_ol[(long long)MROWS * DIM];
__device__ __nv_bfloat16 g_ph[(long long)BATCH * SEQ * SEQ];
__device__ __nv_bfloat16 g_pl[(long long)BATCH * SEQ * SEQ];
__device__ float         g_s [(long long)BATCH * SEQ * SEQ];

// ---------------------------------------------------------------------------
// PTX helpers (sm_80-era: compile clean at compute_103)
// ---------------------------------------------------------------------------
__device__ __forceinline__ uint32_t smem_u32(const void* p) {
    uint32_t a;
    asm("{ .reg .u64 t; cvta.to.shared.u64 t, %1; cvt.u32.u64 %0, t; }" : "=r"(a) : "l"(p));
    return a;
}
__device__ __forceinline__ void cpasync16(uint32_t saddr, const void* g) {
    asm volatile("cp.async.cg.shared.global [%0], [%1], 16;" :: "r"(saddr), "l"(g));
}
#define CP_COMMIT() asm volatile("cp.async.commit_group;" ::: "memory")
#define CP_WAIT(n)  asm volatile("cp.async.wait_group %0;" :: "n"(n) : "memory")

__device__ __forceinline__ void ldsm_x4(uint32_t* r, uint32_t addr) {
    asm volatile("ldmatrix.sync.aligned.m8n8.x4.shared.b16 {%0,%1,%2,%3}, [%4];"
        : "=r"(r[0]), "=r"(r[1]), "=r"(r[2]), "=r"(r[3]) : "r"(addr));
}
__device__ __forceinline__ void ldsm_x2(uint32_t* r, uint32_t addr) {
    asm volatile("ldmatrix.sync.aligned.m8n8.x2.shared.b16 {%0,%1}, [%2];"
        : "=r"(r[0]), "=r"(r[1]) : "r"(addr));
}
__device__ __forceinline__ void mma16816(float* d, const uint32_t* a, const uint32_t* b) {
    asm volatile("mma.sync.aligned.m16n8k16.row.col.f32.bf16.bf16.f32 "
        "{%0,%1,%2,%3}, {%4,%5,%6,%7}, {%8,%9}, {%0,%1,%2,%3};"
        : "+f"(d[0]), "+f"(d[1]), "+f"(d[2]), "+f"(d[3])
        : "r"(a[0]), "r"(a[1]), "r"(a[2]), "r"(a[3]), "r"(b[0]), "r"(b[1]));
}

union U8 { uint4 v; __nv_bfloat16 h[8]; };

__device__ __forceinline__ void split1(float v, __nv_bfloat16& h, __nv_bfloat16& l) {
    h = __float2bfloat16(v);
    l = __float2bfloat16(v - __bfloat162float(h));
}

// ---------------------------------------------------------------------------
// Split fp32 -> bf16 hi/lo  (n divisible by 2048)
// ---------------------------------------------------------------------------
__global__ void __launch_bounds__(256)
split_f32(const float* __restrict__ in, __nv_bfloat16* __restrict__ hi,
          __nv_bfloat16* __restrict__ lo)
{
    long long i = ((long long)blockIdx.x * 256 + threadIdx.x) * 8;
    float4 a = *(const float4*)(in + i);
    float4 b = *(const float4*)(in + i + 4);
    float v[8] = {a.x, a.y, a.z, a.w, b.x, b.y, b.z, b.w};
    U8 uh, ul;
#pragma unroll
    for (int e = 0; e < 8; ++e) split1(v[e], uh.h[e], ul.h[e]);
    *(uint4*)(hi + i) = uh.v;
    *(uint4*)(lo + i) = ul.v;
}

// ---------------------------------------------------------------------------
// Transpose V (hi/lo selected by blockIdx.z): [16384,1024] -> per-batch [1024,2048]
// ---------------------------------------------------------------------------
__global__ void __launch_bounds__(256)
transpose_v(const __nv_bfloat16* __restrict__ inH, const __nv_bfloat16* __restrict__ inL,
            __nv_bfloat16* __restrict__ outH, __nv_bfloat16* __restrict__ outL)
{
    __shared__ __nv_bfloat16 s[64][80];
    const __nv_bfloat16* in  = blockIdx.z ? inL : inH;
    __nv_bfloat16*       out = blockIdx.z ? outL : outH;
    const int tBase = blockIdx.y * 64;          // global token row
    const int dBase = blockIdx.x * 64;          // dim
    const int b  = tBase >> 11;
    const int t0 = tBase & 2047;
    const int tid = threadIdx.x;
#pragma unroll
    for (int p = 0; p < 2; ++p) {
        int task = tid + p * 256;
        int r = task >> 3, cg = task & 7;
        uint4 v = *(const uint4*)(in + (long long)(tBase + r) * DIM + dBase + cg * 8);
        *(uint4*)&s[r][cg * 8] = v;
    }
    __syncthreads();
#pragma unroll
    for (int p = 0; p < 2; ++p) {
        int task = tid + p * 256;
        int d = task >> 3, tg = task & 7;
        U8 u;
#pragma unroll
        for (int e = 0; e < 8; ++e) u.h[e] = s[tg * 8 + e][d];
        *(uint4*)(out + (long long)b * (DIM * SEQ) + (long long)(dBase + d) * SEQ + t0 + tg * 8) = u.v;
    }
}

// ---------------------------------------------------------------------------
// Row softmax over 2048 cols -> bf16 hi/lo output
// ---------------------------------------------------------------------------
__global__ void __launch_bounds__(256)
softmax_split(const float* __restrict__ S, __nv_bfloat16* __restrict__ Ph,
              __nv_bfloat16* __restrict__ Pl, float scale)
{
    const long long row = blockIdx.x;
    const float* p = S + row * (long long)SEQ;
    const int tid = threadIdx.x, lane = tid & 31, wid = tid >> 5;
    __shared__ float buf[8];

    float x[8];
#pragma unroll
    for (int i = 0; i < 8; ++i) x[i] = p[tid + i * 256] * scale;

    float m = x[0];
#pragma unroll
    for (int i = 1; i < 8; ++i) m = fmaxf(m, x[i]);
#pragma unroll
    for (int off = 16; off > 0; off >>= 1)
        m = fmaxf(m, __shfl_xor_sync(0xFFFFFFFFu, m, off));
    if (lane == 0) buf[wid] = m;
    __syncthreads();
    float mfull = buf[0];
#pragma unroll
    for (int w = 1; w < 8; ++w) mfull = fmaxf(mfull, buf[w]);
    __syncthreads();

    float e[8], sum = 0.0f;
#pragma unroll
    for (int i = 0; i < 8; ++i) { e[i] = __expf(x[i] - mfull); sum += e[i]; }
#pragma unroll
    for (int off = 16; off > 0; off >>= 1)
        sum += __shfl_xor_sync(0xFFFFFFFFu, sum, off);
    if (lane == 0) buf[wid] = sum;
    __syncthreads();
    float sfull = 0.0f;
#pragma unroll
    for (int w = 0; w < 8; ++w) sfull += buf[w];
    const float inv = 1.0f / sfull;

    __nv_bfloat16* ph = Ph + row * (long long)SEQ;
    __nv_bfloat16* pl = Pl + row * (long long)SEQ;
#pragma unroll
    for (int i = 0; i < 8; ++i) {
        __nv_bfloat16 h, l;
        split1(e[i] * inv, h, l);
        ph[tid + i * 256] = h;
        pl[tid + i * 256] = l;
    }
}

// ---------------------------------------------------------------------------
// Split-bf16 TN GEMM on mma.sync tensor cores:
//   D[M,N] = (Ah+Al)[M,K] * (Bh+Bl)[N,K]^T  (3-term: AhBh + AhBl + AlBh)
// Tile 128x128, BK=32, 8 warps (2x4 -> warp tile 64x32).
// 3-stage cp.async pipeline, ONE __syncthreads per stage.
// SMEM: 80B-padded rows (proven conflict-free for ldmatrix + cp.async stores),
// coalesced loader (4 consecutive threads cover 64 contiguous bytes of a row).
// EPI=0: fp32 C (+bias).  EPI=1: bf16 hi/lo C (+bias).
// ---------------------------------------------------------------------------
#define MAT_BYTES   10240          // 128 rows * 80 B
#define STAGE_BYTES (4 * MAT_BYTES)
#define NSTAGE 3
#define SMEM_TOTAL  (NSTAGE * STAGE_BYTES)
#define AH_OFF 0
#define AL_OFF MAT_BYTES
#define BH_OFF (2 * MAT_BYTES)
#define BL_OFF (3 * MAT_BYTES)

template<int EPI>
__global__ void __launch_bounds__(256, 1)
gemm_mma(const __nv_bfloat16* __restrict__ Ah, const __nv_bfloat16* __restrict__ Al,
         const __nv_bfloat16* __restrict__ Bh, const __nv_bfloat16* __restrict__ Bl,
         float* __restrict__ Cf, __nv_bfloat16* __restrict__ Ch,
         __nv_bfloat16* __restrict__ Cl, const float* __restrict__ bias,
         int K, int N, long long sA, long long sB, long long sC)
{
    extern __shared__ __align__(128) char smem[];
    const uint32_t sbase = smem_u32(smem);

    const int tid  = threadIdx.x;
    const int wid  = tid >> 5;
    const int lane = tid & 31;
    const int wm   = wid >> 2;      // 0..1
    const int wn   = wid & 3;       // 0..3

    const int bm0 = blockIdx.y * 128;
    const int bn0 = blockIdx.x * 128;
    const long long zA = blockIdx.z * sA, zB = blockIdx.z * sB, zC = blockIdx.z * sC;

    // source row blocks (all 128 rows, K-major)
    const __nv_bfloat16* mats[4];
    mats[0] = Ah + zA + (long long)bm0 * K;
    mats[1] = Al + zA + (long long)bm0 * K;
    mats[2] = Bh + zB + (long long)bn0 * K;
    mats[3] = Bl + zB + (long long)bn0 * K;

    // coalesced loader: thread -> row = tid/4, 16B chunk = tid%4 (rows 0..63, +64)
    const int ldRow0 = tid >> 2;
    const int ldCh   = (tid & 3) * 16;    // byte offset within 64B k-slab

    // ldmatrix base offsets (80B rows)
    const uint32_t aRowOff = (uint32_t)((wm * 64 + (lane & 15)) * 80 + (lane >> 4) * 16);
    const uint32_t bRowOff = (uint32_t)((wn * 32 + (lane & 7)) * 80 + ((lane >> 3) & 1) * 16);

    float acc[4][4][4];
#pragma unroll
    for (int i = 0; i < 4; ++i)
#pragma unroll
        for (int j = 0; j < 4; ++j)
#pragma unroll
            for (int r = 0; r < 4; ++r) acc[i][j][r] = 0.0f;

    const int nStages = K >> 5;

    auto load_stage = [&](int s) {
        const uint32_t sb = sbase + (uint32_t)(s % NSTAGE) * STAGE_BYTES;
        const int k0 = s << 5;
#pragma unroll
        for (int m = 0; m < 4; ++m) {
            const __nv_bfloat16* src = mats[m] + k0;
            const uint32_t dst = sb + m * MAT_BYTES;
            cpasync16(dst + ldRow0 * 80 + ldCh,        src + (long long)ldRow0 * K        + (ldCh >> 1));
            cpasync16(dst + (ldRow0 + 64) * 80 + ldCh, src + (long long)(ldRow0 + 64) * K + (ldCh >> 1));
        }
        CP_COMMIT();
    };

    load_stage(0);
    if (nStages > 1) load_stage(1);

    for (int s = 0; s < nStages; ++s) {
        if (s + 1 < nStages) { CP_WAIT(1); } else { CP_WAIT(0); }
        __syncthreads();
        if (s + 2 < nStages) load_stage(s + 2);

        const uint32_t sb = sbase + (uint32_t)(s % NSTAGE) * STAGE_BYTES;
#pragma unroll
        for (int kb = 0; kb < 2; ++kb) {
            uint32_t bh[4][2], bl[4][2];
#pragma unroll
            for (int j = 0; j < 4; ++j) {
                const uint32_t ba = sb + BH_OFF + bRowOff + (uint32_t)(j * 8 * 80 + kb * 32);
                ldsm_x2(bh[j], ba);
                ldsm_x2(bl[j], ba + MAT_BYTES);
            }
#pragma unroll
            for (int i = 0; i < 4; ++i) {
                const uint32_t aa = sb + AH_OFF + aRowOff + (uint32_t)(i * 16 * 80 + kb * 32);
                uint32_t ah[4], al[4];
                ldsm_x4(ah, aa);
                ldsm_x4(al, aa + MAT_BYTES);
#pragma unroll
                for (int j = 0; j < 4; ++j) {
                    mma16816(acc[i][j], ah, bh[j]);
                    mma16816(acc[i][j], ah, bl[j]);
                    mma16816(acc[i][j], al, bh[j]);
                }
            }
        }
    }

    // ---- epilogue ----
    const int r0base = bm0 + wm * 64 + (lane >> 2);
    const int c0base = bn0 + wn * 32 + (lane & 3) * 2;

    float bz[4][2];
#pragma unroll
    for (int j = 0; j < 4; ++j) {
        const int c = c0base + j * 8;
        bz[j][0] = bias ? __ldg(bias + c)     : 0.0f;
        bz[j][1] = bias ? __ldg(bias + c + 1) : 0.0f;
    }

#pragma unroll
    for (int i = 0; i < 4; ++i) {
        const long long r0 = r0base + i * 16;
        const long long r1 = r0 + 8;
#pragma unroll
        for (int j = 0; j < 4; ++j) {
            const int c = c0base + j * 8;
            float v00 = acc[i][j][0] + bz[j][0];
            float v01 = acc[i][j][1] + bz[j][1];
            float v10 = acc[i][j][2] + bz[j][0];
            float v11 = acc[i][j][3] + bz[j][1];
            if (EPI == 0) {
                *(float2*)(Cf + zC + r0 * N + c) = make_float2(v00, v01);
                *(float2*)(Cf + zC + r1 * N + c) = make_float2(v10, v11);
            } else {
                __nv_bfloat16 h0, l0, h1, l1;
                split1(v00, h0, l0); split1(v01, h1, l1);
                *(__nv_bfloat162*)(Ch + zC + r0 * N + c) = __nv_bfloat162(h0, h1);
                *(__nv_bfloat162*)(Cl + zC + r0 * N + c) = __nv_bfloat162(l0, l1);
                split1(v10, h0, l0); split1(v11, h1, l1);
                *(__nv_bfloat162*)(Ch + zC + r1 * N + c) = __nv_bfloat162(h0, h1);
                *(__nv_bfloat162*)(Cl + zC + r1 * N + c) = __nv_bfloat162(l0, l1);
            }
        }
    }
}

// ---------------------------------------------------------------------------
// kernel_launch
// NOTE launch order: the 6th launch is the Q-projection GEMM so that ncu's
// "-s 5 -c 1" capture profiles gemm_mma instead of an elementwise kernel.
// ---------------------------------------------------------------------------
extern "C" void kernel_launch(void* const* d_in, const int* in_sizes, int n_in,
                              void* d_out, int out_size)
{
    const float* x   = (const float*)d_in[0];
    const float* ctx = (const float*)d_in[1];
    const float* Wq  = (const float*)d_in[2];
    const float* bq  = (const float*)d_in[3];
    const float* Wk  = (const float*)d_in[4];
    const float* bk  = (const float*)d_in[5];
    const float* Wv  = (const float*)d_in[6];
    const float* bv  = (const float*)d_in[7];
    const float* Wo  = (const float*)d_in[8];
    const float* bo  = (const float*)d_in[9];
    float* out = (float*)d_out;

    __nv_bfloat16 *xh, *xl, *ch, *cl, *wqh, *wql, *wkh, *wkl, *wvh, *wvl, *woh, *wol;
    __nv_bfloat16 *qh, *ql, *kh, *kl, *vh, *vl, *vth, *vtl, *oh, *ol, *ph, *pl;
    float* S;
    cudaGetSymbolAddress((void**)&xh, g_xh);   cudaGetSymbolAddress((void**)&xl, g_xl);
    cudaGetSymbolAddress((void**)&ch, g_ch);   cudaGetSymbolAddress((void**)&cl, g_cl);
    cudaGetSymbolAddress((void**)&wqh, g_wqh); cudaGetSymbolAddress((void**)&wql, g_wql);
    cudaGetSymbolAddress((void**)&wkh, g_wkh); cudaGetSymbolAddress((void**)&wkl, g_wkl);
    cudaGetSymbolAddress((void**)&wvh, g_wvh); cudaGetSymbolAddress((void**)&wvl, g_wvl);
    cudaGetSymbolAddress((void**)&woh, g_woh); cudaGetSymbolAddress((void**)&wol, g_wol);
    cudaGetSymbolAddress((void**)&qh, g_qh);   cudaGetSymbolAddress((void**)&ql, g_ql);
    cudaGetSymbolAddress((void**)&kh, g_kh);   cudaGetSymbolAddress((void**)&kl, g_kl);
    cudaGetSymbolAddress((void**)&vh, g_vh);   cudaGetSymbolAddress((void**)&vl, g_vl);
    cudaGetSymbolAddress((void**)&vth, g_vth); cudaGetSymbolAddress((void**)&vtl, g_vtl);
    cudaGetSymbolAddress((void**)&oh, g_oh);   cudaGetSymbolAddress((void**)&ol, g_ol);
    cudaGetSymbolAddress((void**)&ph, g_ph);   cudaGetSymbolAddress((void**)&pl, g_pl);
    cudaGetSymbolAddress((void**)&S, g_s);

    cudaFuncSetAttribute(gemm_mma<0>, cudaFuncAttributeMaxDynamicSharedMemorySize, SMEM_TOTAL);
    cudaFuncSetAttribute(gemm_mma<1>, cudaFuncAttributeMaxDynamicSharedMemorySize, SMEM_TOTAL);

    dim3 grdP(DIM / 128, MROWS / 128, 1);

    // launches 1-5: splits
    split_f32<<<(MROWS * (long long)DIM) / 2048, 256>>>(x, xh, xl);
    split_f32<<<(MROWS * (long long)CTX) / 2048, 256>>>(ctx, ch, cl);
    split_f32<<<(DIM * (long long)DIM) / 2048, 256>>>(Wq, wqh, wql);
    split_f32<<<(DIM * (long long)CTX) / 2048, 256>>>(Wk, wkh, wkl);
    split_f32<<<(DIM * (long long)CTX) / 2048, 256>>>(Wv, wvh, wvl);

    // launch 6: Q projection (profiled by ncu -s 5 -c 1)
    gemm_mma<1><<<grdP, 256, SMEM_TOTAL>>>(xh, xl, wqh, wql, nullptr, qh, ql, bq,
                                           DIM, DIM, 0, 0, 0);

    // remaining split + projections
    split_f32<<<(DIM * (long long)DIM) / 2048, 256>>>(Wo, woh, wol);
    gemm_mma<1><<<grdP, 256, SMEM_TOTAL>>>(ch, cl, wkh, wkl, nullptr, kh, kl, bk,
                                           CTX, DIM, 0, 0, 0);
    gemm_mma<1><<<grdP, 256, SMEM_TOTAL>>>(ch, cl, wvh, wvl, nullptr, vh, vl, bv,
                                           CTX, DIM, 0, 0, 0);

    // transpose V per batch -> [DIM, SEQ]
    transpose_v<<<dim3(DIM / 64, MROWS / 64, 2), 256>>>(vh, vl, vth, vtl);

    // scores S = Q K^T (fp32)
    {
        dim3 grd(SEQ / 128, SEQ / 128, BATCH);
        gemm_mma<0><<<grd, 256, SMEM_TOTAL>>>(qh, ql, kh, kl, S, nullptr, nullptr, nullptr,
                                              DIM, SEQ,
                                              (long long)SEQ * DIM, (long long)SEQ * DIM,
                                              (long long)SEQ * SEQ);
    }

    // softmax -> P hi/lo
    softmax_split<<<BATCH * SEQ, 256>>>(S, ph, pl, 1.0f / sqrtf((float)DIM));

    // O = P V  -> bf16 hi/lo
    {
        dim3 grd(DIM / 128, SEQ / 128, BATCH);
        gemm_mma<1><<<grd, 256, SMEM_TOTAL>>>(ph, pl, vth, vtl, nullptr, oh, ol, nullptr,
                                              SEQ, DIM,
                                              (long long)SEQ * SEQ, (long long)DIM * SEQ,
                                              (long long)SEQ * DIM);
    }

    // out = O Wo^T + bo (fp32 -> d_out)
    gemm_mma<0><<<grdP, 256, SMEM_TOTAL>>>(oh, ol, woh, wol, out, nullptr, nullptr, bo,
                                           DIM, DIM, 0, 0, 0);
}